// round 12
// baseline (speedup 1.0000x reference)
#include <cuda_runtime.h>
#include <cuda_bf16.h>
#include <cuda_fp16.h>
#include <cstdint>

#define N_NODES 50000
#define D 128
#define N_EDGES 640000
#define S_BLK 64                       // sort blocks (wave-1 resident: < 148)
#define GRID_TOT 296
#define NGB ((N_NODES + 127) / 128)    // 391 gemm tiles
#define CHUNK 4                        // scan items per sort thread
#define NT (S_BLK * 256)               // sort threads = 16384

// Packed fp32x2 FMA (sm_100+): one fma-pipe slot computes two lane-FMAs.
#define FMA2(acc, a, b) \
    asm("fma.rn.f32x2 %0, %1, %2, %0;" : "+l"(acc) : "l"(a), "l"(b))
#define SPLAT2(d, f) \
    asm("mov.b64 %0, {%1, %1};" : "=l"(d) : "f"(f))
#define UNPACK2(lo, hi, v) \
    asm("mov.b64 {%0, %1}, %2;" : "=f"(lo), "=f"(hi) : "l"(v))

// ---- device scratch (no allocs allowed; zero-initialized) ----
__device__ __half g_Yh[(size_t)N_NODES * D];  // feat @ W in fp16 (12.8 MB)
__device__ int   g_count[N_NODES];
__device__ int   g_offset[N_NODES];
__device__ int   g_bsum[S_BLK];
__device__ int   g_bbase[S_BLK];
__device__ int   g_src_sorted[N_EDGES];
__device__ int   g_is64;
__device__ unsigned g_bar_cnt;
__device__ unsigned g_tile;
__device__ unsigned g_done;

__device__ __forceinline__ void sort_barrier(unsigned target) {
    __syncthreads();
    if (threadIdx.x == 0) {
        __threadfence();
        atomicAdd(&g_bar_cnt, 1u);
        while (*((volatile unsigned*)&g_bar_cnt) < target) __nanosleep(64);
        __threadfence();
    }
    __syncthreads();
}

// ---------------------------------------------------------------------------
// Mega kernel: blocks [0,S_BLK) run the sort chain then join the gemm pool;
// the rest run gemm tiles (g_Yh = fp16(feat @ W)) from a stealing counter.
// gemm: 128x128 tile, 8x8 reg tile as 8x4 f32x2 pairs, Kc=32 in smem,
// software-pipelined global->reg prefetch of the next k-chunk.
// ---------------------------------------------------------------------------
__global__ void __launch_bounds__(256)
mega_kernel(const float* __restrict__ feat, const float* __restrict__ W,
            const void* __restrict__ srcp, const void* __restrict__ dstp) {
    __shared__ float sA[128 * 33];   // A tile, stride-33 padded
    __shared__ float sB[32 * 128];   // B tile [k][col]
    __shared__ int   ss[256];        // sort scan workspace

    const int tid = threadIdx.x;

    if (blockIdx.x < S_BLK) {
        // ================= SORT CHAIN (proven, unchanged) =================
        const int b = blockIdx.x;
        const int st = b * 256 + tid;

        for (int i = st; i < N_NODES; i += NT) g_count[i] = 0;
        if (b == 0 && tid < 32) {
            // int32 read as int64 packs two indices; high half is a random
            // node index (nonzero w.p. ~1-2e-5) -> out-of-range identifies it.
            const long long* s64 = (const long long*)srcp;
            const long long* d64 = (const long long*)dstp;
            int bad = 0;
#pragma unroll
            for (int r = 0; r < 2; r++) {
                int i = tid + r * 32;
                long long a = s64[i], c = d64[i];
                bad |= (a < 0 || a >= N_NODES || c < 0 || c >= N_NODES);
            }
            unsigned m = __ballot_sync(0xFFFFFFFFu, bad);
            if (tid == 0) g_is64 = (m == 0u);
        }
        sort_barrier(1u * S_BLK);

        const int is64 = g_is64;
        {   // hist (4x batched for MLP)
            int e = st;
            if (is64) {
                const long long* dd = (const long long*)dstp;
                for (; e + 3 * NT < N_EDGES; e += 4 * NT) {
                    int d0 = (int)dd[e], d1 = (int)dd[e + NT];
                    int d2 = (int)dd[e + 2 * NT], d3 = (int)dd[e + 3 * NT];
                    atomicAdd(&g_count[d0], 1); atomicAdd(&g_count[d1], 1);
                    atomicAdd(&g_count[d2], 1); atomicAdd(&g_count[d3], 1);
                }
                for (; e < N_EDGES; e += NT) atomicAdd(&g_count[(int)dd[e]], 1);
            } else {
                const int* dd = (const int*)dstp;
                for (; e + 3 * NT < N_EDGES; e += 4 * NT) {
                    int d0 = dd[e], d1 = dd[e + NT];
                    int d2 = dd[e + 2 * NT], d3 = dd[e + 3 * NT];
                    atomicAdd(&g_count[d0], 1); atomicAdd(&g_count[d1], 1);
                    atomicAdd(&g_count[d2], 1); atomicAdd(&g_count[d3], 1);
                }
                for (; e < N_EDGES; e += NT) atomicAdd(&g_count[dd[e]], 1);
            }
        }
        sort_barrier(2u * S_BLK);

        // scan: per-thread sums + block scan
        const int g0 = st * CHUNK;
        int csum = 0, cv[CHUNK];
#pragma unroll
        for (int i = 0; i < CHUNK; i++) {
            int g = g0 + i;
            cv[i] = (g < N_NODES) ? g_count[g] : 0;
            csum += cv[i];
        }
        ss[tid] = csum;
        __syncthreads();
#pragma unroll
        for (int off = 1; off < 256; off <<= 1) {
            int v = ss[tid];
            int u = (tid >= off) ? ss[tid - off] : 0;
            __syncthreads();
            ss[tid] = v + u;
            __syncthreads();
        }
        const int texcl = ss[tid] - csum;
        if (tid == 255) g_bsum[b] = ss[255];
        sort_barrier(3u * S_BLK);

        if (b == 0) {
            int v0 = (tid < S_BLK) ? g_bsum[tid] : 0;
            ss[tid] = v0;
            __syncthreads();
#pragma unroll
            for (int off = 1; off < S_BLK; off <<= 1) {
                int v = ss[tid];
                int u = (tid >= off) ? ss[tid - off] : 0;
                __syncthreads();
                ss[tid] = v + u;
                __syncthreads();
            }
            if (tid < S_BLK) g_bbase[tid] = ss[tid] - v0;
        }
        sort_barrier(4u * S_BLK);

        {
            int run = g_bbase[b] + texcl;
#pragma unroll
            for (int i = 0; i < CHUNK; i++) {
                int g = g0 + i;
                if (g < N_NODES) g_offset[g] = run;
                run += cv[i];
            }
        }
        sort_barrier(5u * S_BLK);

        {   // scatter (4x batched)
            int e = st;
            if (is64) {
                const long long* dd = (const long long*)dstp;
                const long long* sv = (const long long*)srcp;
                for (; e + 3 * NT < N_EDGES; e += 4 * NT) {
                    int d0 = (int)dd[e],          s0 = (int)sv[e];
                    int d1 = (int)dd[e + NT],     s1 = (int)sv[e + NT];
                    int d2 = (int)dd[e + 2 * NT], s2 = (int)sv[e + 2 * NT];
                    int d3 = (int)dd[e + 3 * NT], s3 = (int)sv[e + 3 * NT];
                    int p0 = atomicAdd(&g_offset[d0], 1);
                    int p1 = atomicAdd(&g_offset[d1], 1);
                    int p2 = atomicAdd(&g_offset[d2], 1);
                    int p3 = atomicAdd(&g_offset[d3], 1);
                    g_src_sorted[p0] = s0; g_src_sorted[p1] = s1;
                    g_src_sorted[p2] = s2; g_src_sorted[p3] = s3;
                }
                for (; e < N_EDGES; e += NT)
                    g_src_sorted[atomicAdd(&g_offset[(int)dd[e]], 1)] = (int)sv[e];
            } else {
                const int* dd = (const int*)dstp;
                const int* sv = (const int*)srcp;
                for (; e + 3 * NT < N_EDGES; e += 4 * NT) {
                    int d0 = dd[e],          s0 = sv[e];
                    int d1 = dd[e + NT],     s1 = sv[e + NT];
                    int d2 = dd[e + 2 * NT], s2 = sv[e + 2 * NT];
                    int d3 = dd[e + 3 * NT], s3 = sv[e + 3 * NT];
                    int p0 = atomicAdd(&g_offset[d0], 1);
                    int p1 = atomicAdd(&g_offset[d1], 1);
                    int p2 = atomicAdd(&g_offset[d2], 1);
                    int p3 = atomicAdd(&g_offset[d3], 1);
                    g_src_sorted[p0] = s0; g_src_sorted[p1] = s1;
                    g_src_sorted[p2] = s2; g_src_sorted[p3] = s3;
                }
                for (; e < N_EDGES; e += NT)
                    g_src_sorted[atomicAdd(&g_offset[dd[e]], 1)] = sv[e];
            }
        }
        __syncthreads();
        // fall through: join the gemm tile pool
    }

    // ====== GEMM: g_Yh = fp16(feat @ W), f32x2 FMA, pipelined staging ======
    const int tx = tid & 15;          // col group (8 cols = 4 f32x2 pairs)
    const int ty = tid >> 4;          // row group (8 rows)
    const int kq = tid & 7;           // A stage: f4 index in k-chunk
    const int ar0 = tid >> 3;         // A stage: row 0..31
    const int c4 = tid & 31;          // B stage: f4 col
    const int kr0 = tid >> 5;         // B stage: k row 0..7

    __shared__ unsigned s_tile;
    for (;;) {
        __syncthreads();
        if (tid == 0) s_tile = atomicAdd(&g_tile, 1u);
        __syncthreads();
        const unsigned tile = s_tile;
        if (tile >= NGB) break;
        const int row0 = (int)tile * 128;

        unsigned long long acc2[8][4];   // acc2[i][jp] = cols (2jp, 2jp+1)
#pragma unroll
        for (int i = 0; i < 8; i++)
#pragma unroll
            for (int j = 0; j < 4; j++) acc2[i][j] = 0ull;

        // prefetch chunk 0 into registers
        float4 pa[4], pb[4];
#pragma unroll
        for (int p = 0; p < 4; p++) {
            int row = row0 + ar0 + p * 32;
            pa[p] = (row < N_NODES)
                ? *(const float4*)(feat + (size_t)row * D + kq * 4)
                : make_float4(0.f, 0.f, 0.f, 0.f);
            pb[p] = *(const float4*)(W + (size_t)(kr0 + p * 8) * D + c4 * 4);
        }

        for (int c = 0; c < 4; c++) {
            // store prefetched chunk to smem
#pragma unroll
            for (int p = 0; p < 4; p++) {
                float* dstA = &sA[(ar0 + p * 32) * 33 + kq * 4];
                dstA[0] = pa[p].x; dstA[1] = pa[p].y;
                dstA[2] = pa[p].z; dstA[3] = pa[p].w;
                *(float4*)(sB + (kr0 + p * 8) * 128 + c4 * 4) = pb[p];
            }
            __syncthreads();

            // issue next chunk's global loads (hide under compute)
            if (c < 3) {
                const int k0n = (c + 1) * 32;
#pragma unroll
                for (int p = 0; p < 4; p++) {
                    int row = row0 + ar0 + p * 32;
                    pa[p] = (row < N_NODES)
                        ? *(const float4*)(feat + (size_t)row * D + k0n + kq * 4)
                        : make_float4(0.f, 0.f, 0.f, 0.f);
                    pb[p] = *(const float4*)(W + (size_t)(k0n + kr0 + p * 8) * D + c4 * 4);
                }
            }

#pragma unroll 8
            for (int k = 0; k < 32; k++) {
                ulonglong2 bl0 = *(const ulonglong2*)(sB + k * 128 + tx * 8);
                ulonglong2 bl1 = *(const ulonglong2*)(sB + k * 128 + tx * 8 + 4);
                unsigned long long b2[4] = {bl0.x, bl0.y, bl1.x, bl1.y};
                unsigned long long a2[8];
#pragma unroll
                for (int i = 0; i < 8; i++) {
                    float av = sA[(ty * 8 + i) * 33 + k];
                    SPLAT2(a2[i], av);
                }
#pragma unroll
                for (int i = 0; i < 8; i++)
#pragma unroll
                    for (int j = 0; j < 4; j++) FMA2(acc2[i][j], a2[i], b2[j]);
            }
            __syncthreads();
        }

        // fp16 epilogue: each acc2 pair -> one half2; 16B store per row seg
#pragma unroll
        for (int i = 0; i < 8; i++) {
            int row = row0 + ty * 8 + i;
            if (row < N_NODES) {
                __half2 h[4];
#pragma unroll
                for (int j = 0; j < 4; j++) {
                    float lo, hi;
                    UNPACK2(lo, hi, acc2[i][j]);
                    h[j] = __floats2half2_rn(lo, hi);
                }
                *(uint4*)(g_Yh + (size_t)row * D + tx * 8) = *(uint4*)h;
            }
        }
    }

    // counter reset for next graph replay
    __syncthreads();
    if (tid == 0) {
        __threadfence();
        unsigned old = atomicAdd(&g_done, 1u);
        if (old == GRID_TOT - 1) { g_tile = 0; g_bar_cnt = 0; g_done = 0; }
    }
}

// ---------------------------------------------------------------------------
// Aggregation: out[n] = sum_{e in seg(n)} Yh[src_sorted[e]] + b.
// One warp per node; lane covers 4 cols (8B). 4-wide edge batching keeps
// 4 independent row LDGs in flight (loop is L2-latency-bound).
// ---------------------------------------------------------------------------
__global__ void __launch_bounds__(256) agg_kernel(const float* __restrict__ bias,
                                                  float* __restrict__ out) {
    int node = (blockIdx.x * blockDim.x + threadIdx.x) >> 5;
    int lane = threadIdx.x & 31;
    if (node >= N_NODES) return;

    const int end = g_offset[node];
    const int beg = end - g_count[node];

    float4 acc0 = make_float4(0.f, 0.f, 0.f, 0.f);
    float4 acc1 = make_float4(0.f, 0.f, 0.f, 0.f);
    int e = beg;
    for (; e + 3 < end; e += 4) {
        int s0 = g_src_sorted[e];
        int s1 = g_src_sorted[e + 1];
        int s2 = g_src_sorted[e + 2];
        int s3 = g_src_sorted[e + 3];
        uint2 v0 = ((const uint2*)(g_Yh + (size_t)s0 * D))[lane];
        uint2 v1 = ((const uint2*)(g_Yh + (size_t)s1 * D))[lane];
        uint2 v2 = ((const uint2*)(g_Yh + (size_t)s2 * D))[lane];
        uint2 v3 = ((const uint2*)(g_Yh + (size_t)s3 * D))[lane];
        float2 a0 = __half22float2(*(__half2*)&v0.x), b0 = __half22float2(*(__half2*)&v0.y);
        float2 a1 = __half22float2(*(__half2*)&v1.x), b1 = __half22float2(*(__half2*)&v1.y);
        float2 a2 = __half22float2(*(__half2*)&v2.x), b2 = __half22float2(*(__half2*)&v2.y);
        float2 a3 = __half22float2(*(__half2*)&v3.x), b3 = __half22float2(*(__half2*)&v3.y);
        acc0.x += a0.x + a1.x; acc0.y += a0.y + a1.y;
        acc0.z += b0.x + b1.x; acc0.w += b0.y + b1.y;
        acc1.x += a2.x + a3.x; acc1.y += a2.y + a3.y;
        acc1.z += b2.x + b3.x; acc1.w += b2.y + b3.y;
    }
    for (; e < end; e++) {
        int s = g_src_sorted[e];
        uint2 v = ((const uint2*)(g_Yh + (size_t)s * D))[lane];
        float2 a = __half22float2(*(__half2*)&v.x);
        float2 b = __half22float2(*(__half2*)&v.y);
        acc0.x += a.x; acc0.y += a.y; acc0.z += b.x; acc0.w += b.y;
    }

    float4 bv = ((const float4*)bias)[lane];
    ((float4*)(out + (size_t)node * D))[lane] = make_float4(
        acc0.x + acc1.x + bv.x, acc0.y + acc1.y + bv.y,
        acc0.z + acc1.z + bv.z, acc0.w + acc1.w + bv.w);
}

// ---------------------------------------------------------------------------
// Launch: 2 kernels, graph-capturable (no sync, no alloc).
// ---------------------------------------------------------------------------
extern "C" void kernel_launch(void* const* d_in, const int* in_sizes, int n_in,
                              void* d_out, int out_size) {
    const float* feat = (const float*)d_in[0];  // [50000, 128] f32
    const void*  src  = d_in[1];                // [640000] int32/int64
    const void*  dst  = d_in[2];                // [640000] int32/int64
    const float* W    = (const float*)d_in[3];  // [128, 128] f32
    const float* b    = (const float*)d_in[4];  // [1, 128] f32
    float* out = (float*)d_out;                 // [50000, 128] f32

    mega_kernel<<<GRID_TOT, 256>>>(feat, W, src, dst);
    agg_kernel<<<(N_NODES * 32 + 255) / 256, 256>>>(b, out);
}

// round 13
// speedup vs baseline: 1.2014x; 1.2014x over previous
#include <cuda_runtime.h>
#include <cuda_bf16.h>
#include <cuda_fp16.h>
#include <cstdint>

#define N_NODES 50000
#define D 128
#define N_EDGES 640000
#define S_BLK 64                       // sort blocks (wave-1 resident: < 148)
#define GRID_TOT 296
#define NGB ((N_NODES + 127) / 128)    // 391 gemm tiles
#define CHUNK 4                        // scan items per sort thread
#define NT (S_BLK * 256)               // sort threads = 16384

// Packed fp32x2 FMA (sm_100+): one fma-pipe slot computes two lane-FMAs.
#define FMA2(acc, a, b) \
    asm("fma.rn.f32x2 %0, %1, %2, %0;" : "+l"(acc) : "l"(a), "l"(b))
#define SPLAT2(d, f) \
    asm("mov.b64 %0, {%1, %1};" : "=l"(d) : "f"(f))
#define UNPACK2(lo, hi, v) \
    asm("mov.b64 {%0, %1}, %2;" : "=f"(lo), "=f"(hi) : "l"(v))

// ---- device scratch (no allocs allowed; zero-initialized) ----
__device__ __half g_Yh[(size_t)N_NODES * D];  // feat @ W in fp16 (12.8 MB)
__device__ int   g_count[N_NODES];
__device__ int   g_offset[N_NODES];
__device__ int   g_bsum[S_BLK];
__device__ int   g_bbase[S_BLK];
__device__ int   g_src_sorted[N_EDGES];
__device__ int   g_is64;
__device__ unsigned g_bar_cnt;
__device__ unsigned g_tile;
__device__ unsigned g_done;

__device__ __forceinline__ void sort_barrier(unsigned target) {
    __syncthreads();
    if (threadIdx.x == 0) {
        __threadfence();
        atomicAdd(&g_bar_cnt, 1u);
        while (*((volatile unsigned*)&g_bar_cnt) < target) __nanosleep(64);
        __threadfence();
    }
    __syncthreads();
}

// ---------------------------------------------------------------------------
// Mega kernel (EXACT round-11 structure — the measured best for this part).
//  blocks [0,S_BLK): sort chain then join gemm pool; rest: gemm tiles.
//  gemm: g_Yh = fp16(feat @ W), 128x128 tile, 8x4 f32x2 reg tile, Kc=32.
// ---------------------------------------------------------------------------
__global__ void __launch_bounds__(256)
mega_kernel(const float* __restrict__ feat, const float* __restrict__ W,
            const void* __restrict__ srcp, const void* __restrict__ dstp) {
    __shared__ float sA[128 * 33];   // A tile, stride-33 padded
    __shared__ float sB[32 * 128];   // B tile [k][col]
    __shared__ int   ss[256];        // sort scan workspace

    const int tid = threadIdx.x;

    if (blockIdx.x < S_BLK) {
        // ================= SORT CHAIN (proven, unchanged) =================
        const int b = blockIdx.x;
        const int st = b * 256 + tid;

        for (int i = st; i < N_NODES; i += NT) g_count[i] = 0;
        if (b == 0 && tid < 32) {
            // int32 read as int64 packs two indices; high half is a random
            // node index (nonzero w.p. ~1-2e-5) -> out-of-range identifies it.
            const long long* s64 = (const long long*)srcp;
            const long long* d64 = (const long long*)dstp;
            int bad = 0;
#pragma unroll
            for (int r = 0; r < 2; r++) {
                int i = tid + r * 32;
                long long a = s64[i], c = d64[i];
                bad |= (a < 0 || a >= N_NODES || c < 0 || c >= N_NODES);
            }
            unsigned m = __ballot_sync(0xFFFFFFFFu, bad);
            if (tid == 0) g_is64 = (m == 0u);
        }
        sort_barrier(1u * S_BLK);

        const int is64 = g_is64;
        {   // hist (4x batched for MLP)
            int e = st;
            if (is64) {
                const long long* dd = (const long long*)dstp;
                for (; e + 3 * NT < N_EDGES; e += 4 * NT) {
                    int d0 = (int)dd[e], d1 = (int)dd[e + NT];
                    int d2 = (int)dd[e + 2 * NT], d3 = (int)dd[e + 3 * NT];
                    atomicAdd(&g_count[d0], 1); atomicAdd(&g_count[d1], 1);
                    atomicAdd(&g_count[d2], 1); atomicAdd(&g_count[d3], 1);
                }
                for (; e < N_EDGES; e += NT) atomicAdd(&g_count[(int)dd[e]], 1);
            } else {
                const int* dd = (const int*)dstp;
                for (; e + 3 * NT < N_EDGES; e += 4 * NT) {
                    int d0 = dd[e], d1 = dd[e + NT];
                    int d2 = dd[e + 2 * NT], d3 = dd[e + 3 * NT];
                    atomicAdd(&g_count[d0], 1); atomicAdd(&g_count[d1], 1);
                    atomicAdd(&g_count[d2], 1); atomicAdd(&g_count[d3], 1);
                }
                for (; e < N_EDGES; e += NT) atomicAdd(&g_count[dd[e]], 1);
            }
        }
        sort_barrier(2u * S_BLK);

        // scan: per-thread sums + block scan
        const int g0 = st * CHUNK;
        int csum = 0, cv[CHUNK];
#pragma unroll
        for (int i = 0; i < CHUNK; i++) {
            int g = g0 + i;
            cv[i] = (g < N_NODES) ? g_count[g] : 0;
            csum += cv[i];
        }
        ss[tid] = csum;
        __syncthreads();
#pragma unroll
        for (int off = 1; off < 256; off <<= 1) {
            int v = ss[tid];
            int u = (tid >= off) ? ss[tid - off] : 0;
            __syncthreads();
            ss[tid] = v + u;
            __syncthreads();
        }
        const int texcl = ss[tid] - csum;
        if (tid == 255) g_bsum[b] = ss[255];
        sort_barrier(3u * S_BLK);

        if (b == 0) {
            int v0 = (tid < S_BLK) ? g_bsum[tid] : 0;
            ss[tid] = v0;
            __syncthreads();
#pragma unroll
            for (int off = 1; off < S_BLK; off <<= 1) {
                int v = ss[tid];
                int u = (tid >= off) ? ss[tid - off] : 0;
                __syncthreads();
                ss[tid] = v + u;
                __syncthreads();
            }
            if (tid < S_BLK) g_bbase[tid] = ss[tid] - v0;
        }
        sort_barrier(4u * S_BLK);

        {
            int run = g_bbase[b] + texcl;
#pragma unroll
            for (int i = 0; i < CHUNK; i++) {
                int g = g0 + i;
                if (g < N_NODES) g_offset[g] = run;
                run += cv[i];
            }
        }
        sort_barrier(5u * S_BLK);

        {   // scatter (4x batched)
            int e = st;
            if (is64) {
                const long long* dd = (const long long*)dstp;
                const long long* sv = (const long long*)srcp;
                for (; e + 3 * NT < N_EDGES; e += 4 * NT) {
                    int d0 = (int)dd[e],          s0 = (int)sv[e];
                    int d1 = (int)dd[e + NT],     s1 = (int)sv[e + NT];
                    int d2 = (int)dd[e + 2 * NT], s2 = (int)sv[e + 2 * NT];
                    int d3 = (int)dd[e + 3 * NT], s3 = (int)sv[e + 3 * NT];
                    int p0 = atomicAdd(&g_offset[d0], 1);
                    int p1 = atomicAdd(&g_offset[d1], 1);
                    int p2 = atomicAdd(&g_offset[d2], 1);
                    int p3 = atomicAdd(&g_offset[d3], 1);
                    g_src_sorted[p0] = s0; g_src_sorted[p1] = s1;
                    g_src_sorted[p2] = s2; g_src_sorted[p3] = s3;
                }
                for (; e < N_EDGES; e += NT)
                    g_src_sorted[atomicAdd(&g_offset[(int)dd[e]], 1)] = (int)sv[e];
            } else {
                const int* dd = (const int*)dstp;
                const int* sv = (const int*)srcp;
                for (; e + 3 * NT < N_EDGES; e += 4 * NT) {
                    int d0 = dd[e],          s0 = sv[e];
                    int d1 = dd[e + NT],     s1 = sv[e + NT];
                    int d2 = dd[e + 2 * NT], s2 = sv[e + 2 * NT];
                    int d3 = dd[e + 3 * NT], s3 = sv[e + 3 * NT];
                    int p0 = atomicAdd(&g_offset[d0], 1);
                    int p1 = atomicAdd(&g_offset[d1], 1);
                    int p2 = atomicAdd(&g_offset[d2], 1);
                    int p3 = atomicAdd(&g_offset[d3], 1);
                    g_src_sorted[p0] = s0; g_src_sorted[p1] = s1;
                    g_src_sorted[p2] = s2; g_src_sorted[p3] = s3;
                }
                for (; e < N_EDGES; e += NT)
                    g_src_sorted[atomicAdd(&g_offset[dd[e]], 1)] = sv[e];
            }
        }
        __syncthreads();
        // fall through: join the gemm tile pool
    }

    // ====== GEMM: g_Yh = fp16(feat @ W), f32x2 FMA, work-stealing ======
    const int tx = tid & 15;          // col group (8 cols = 4 f32x2 pairs)
    const int ty = tid >> 4;          // row group (8 rows)
    const int kq = tid & 7;           // A stage: f4 index in k-chunk
    const int ar0 = tid >> 3;         // A stage: row 0..31
    const int c4 = tid & 31;          // B stage: f4 col
    const int kr0 = tid >> 5;         // B stage: k row 0..7

    __shared__ unsigned s_tile;
    for (;;) {
        __syncthreads();
        if (tid == 0) s_tile = atomicAdd(&g_tile, 1u);
        __syncthreads();
        const unsigned tile = s_tile;
        if (tile >= NGB) break;
        const int row0 = (int)tile * 128;

        unsigned long long acc2[8][4];   // acc2[i][jp] = cols (2jp, 2jp+1)
#pragma unroll
        for (int i = 0; i < 8; i++)
#pragma unroll
            for (int j = 0; j < 4; j++) acc2[i][j] = 0ull;

        for (int k0 = 0; k0 < D; k0 += 32) {
#pragma unroll
            for (int p = 0; p < 4; p++) {
                int r = ar0 + p * 32;
                int row = row0 + r;
                float4 v = make_float4(0.f, 0.f, 0.f, 0.f);
                if (row < N_NODES)
                    v = *(const float4*)(feat + (size_t)row * D + k0 + kq * 4);
                float* dst = &sA[r * 33 + kq * 4];
                dst[0] = v.x; dst[1] = v.y; dst[2] = v.z; dst[3] = v.w;
            }
#pragma unroll
            for (int p = 0; p < 4; p++) {
                int kr = kr0 + p * 8;
                *(float4*)(sB + kr * 128 + c4 * 4) =
                    *(const float4*)(W + (size_t)(k0 + kr) * D + c4 * 4);
            }
            __syncthreads();

#pragma unroll 8
            for (int k = 0; k < 32; k++) {
                ulonglong2 bl0 = *(const ulonglong2*)(sB + k * 128 + tx * 8);
                ulonglong2 bl1 = *(const ulonglong2*)(sB + k * 128 + tx * 8 + 4);
                unsigned long long b2[4] = {bl0.x, bl0.y, bl1.x, bl1.y};
                unsigned long long a2[8];
#pragma unroll
                for (int i = 0; i < 8; i++) {
                    float av = sA[(ty * 8 + i) * 33 + k];
                    SPLAT2(a2[i], av);
                }
#pragma unroll
                for (int i = 0; i < 8; i++)
#pragma unroll
                    for (int j = 0; j < 4; j++) FMA2(acc2[i][j], a2[i], b2[j]);
            }
            __syncthreads();
        }

        // fp16 epilogue: each acc2 pair -> one half2; 16B store per row seg
#pragma unroll
        for (int i = 0; i < 8; i++) {
            int row = row0 + ty * 8 + i;
            if (row < N_NODES) {
                __half2 h[4];
#pragma unroll
                for (int j = 0; j < 4; j++) {
                    float lo, hi;
                    UNPACK2(lo, hi, acc2[i][j]);
                    h[j] = __floats2half2_rn(lo, hi);
                }
                *(uint4*)(g_Yh + (size_t)row * D + tx * 8) = *(uint4*)h;
            }
        }
    }

    // counter reset for next graph replay
    __syncthreads();
    if (tid == 0) {
        __threadfence();
        unsigned old = atomicAdd(&g_done, 1u);
        if (old == GRID_TOT - 1) { g_tile = 0; g_bar_cnt = 0; g_done = 0; }
    }
}

// ---------------------------------------------------------------------------
// Aggregation: out[n] = sum_{e in seg(n)} Yh[src_sorted[e]] + b.
// One warp per node; lane covers 4 cols (8B). 8-wide edge batching keeps
// 8 independent row LDGs in flight (loop is L2-latency-bound, mean deg 12.8).
// ---------------------------------------------------------------------------
__global__ void __launch_bounds__(256) agg_kernel(const float* __restrict__ bias,
                                                  float* __restrict__ out) {
    int node = (blockIdx.x * blockDim.x + threadIdx.x) >> 5;
    int lane = threadIdx.x & 31;
    if (node >= N_NODES) return;

    const int end = g_offset[node];
    const int beg = end - g_count[node];

    float4 acc0 = make_float4(0.f, 0.f, 0.f, 0.f);
    float4 acc1 = make_float4(0.f, 0.f, 0.f, 0.f);
    int e = beg;
    for (; e + 7 < end; e += 8) {
        int s0 = g_src_sorted[e];
        int s1 = g_src_sorted[e + 1];
        int s2 = g_src_sorted[e + 2];
        int s3 = g_src_sorted[e + 3];
        int s4 = g_src_sorted[e + 4];
        int s5 = g_src_sorted[e + 5];
        int s6 = g_src_sorted[e + 6];
        int s7 = g_src_sorted[e + 7];
        uint2 v0 = ((const uint2*)(g_Yh + (size_t)s0 * D))[lane];
        uint2 v1 = ((const uint2*)(g_Yh + (size_t)s1 * D))[lane];
        uint2 v2 = ((const uint2*)(g_Yh + (size_t)s2 * D))[lane];
        uint2 v3 = ((const uint2*)(g_Yh + (size_t)s3 * D))[lane];
        uint2 v4 = ((const uint2*)(g_Yh + (size_t)s4 * D))[lane];
        uint2 v5 = ((const uint2*)(g_Yh + (size_t)s5 * D))[lane];
        uint2 v6 = ((const uint2*)(g_Yh + (size_t)s6 * D))[lane];
        uint2 v7 = ((const uint2*)(g_Yh + (size_t)s7 * D))[lane];
        float2 a0 = __half22float2(*(__half2*)&v0.x), b0 = __half22float2(*(__half2*)&v0.y);
        float2 a1 = __half22float2(*(__half2*)&v1.x), b1 = __half22float2(*(__half2*)&v1.y);
        float2 a2 = __half22float2(*(__half2*)&v2.x), b2 = __half22float2(*(__half2*)&v2.y);
        float2 a3 = __half22float2(*(__half2*)&v3.x), b3 = __half22float2(*(__half2*)&v3.y);
        float2 a4 = __half22float2(*(__half2*)&v4.x), b4 = __half22float2(*(__half2*)&v4.y);
        float2 a5 = __half22float2(*(__half2*)&v5.x), b5 = __half22float2(*(__half2*)&v5.y);
        float2 a6 = __half22float2(*(__half2*)&v6.x), b6 = __half22float2(*(__half2*)&v6.y);
        float2 a7 = __half22float2(*(__half2*)&v7.x), b7 = __half22float2(*(__half2*)&v7.y);
        acc0.x += (a0.x + a1.x) + (a2.x + a3.x);
        acc0.y += (a0.y + a1.y) + (a2.y + a3.y);
        acc0.z += (b0.x + b1.x) + (b2.x + b3.x);
        acc0.w += (b0.y + b1.y) + (b2.y + b3.y);
        acc1.x += (a4.x + a5.x) + (a6.x + a7.x);
        acc1.y += (a4.y + a5.y) + (a6.y + a7.y);
        acc1.z += (b4.x + b5.x) + (b6.x + b7.x);
        acc1.w += (b4.y + b5.y) + (b6.y + b7.y);
    }
    for (; e + 3 < end; e += 4) {
        int s0 = g_src_sorted[e];
        int s1 = g_src_sorted[e + 1];
        int s2 = g_src_sorted[e + 2];
        int s3 = g_src_sorted[e + 3];
        uint2 v0 = ((const uint2*)(g_Yh + (size_t)s0 * D))[lane];
        uint2 v1 = ((const uint2*)(g_Yh + (size_t)s1 * D))[lane];
        uint2 v2 = ((const uint2*)(g_Yh + (size_t)s2 * D))[lane];
        uint2 v3 = ((const uint2*)(g_Yh + (size_t)s3 * D))[lane];
        float2 a0 = __half22float2(*(__half2*)&v0.x), b0 = __half22float2(*(__half2*)&v0.y);
        float2 a1 = __half22float2(*(__half2*)&v1.x), b1 = __half22float2(*(__half2*)&v1.y);
        float2 a2 = __half22float2(*(__half2*)&v2.x), b2 = __half22float2(*(__half2*)&v2.y);
        float2 a3 = __half22float2(*(__half2*)&v3.x), b3 = __half22float2(*(__half2*)&v3.y);
        acc0.x += (a0.x + a1.x) + (a2.x + a3.x);
        acc0.y += (a0.y + a1.y) + (a2.y + a3.y);
        acc0.z += (b0.x + b1.x) + (b2.x + b3.x);
        acc0.w += (b0.y + b1.y) + (b2.y + b3.y);
    }
    for (; e < end; e++) {
        int s = g_src_sorted[e];
        uint2 v = ((const uint2*)(g_Yh + (size_t)s * D))[lane];
        float2 a = __half22float2(*(__half2*)&v.x);
        float2 b = __half22float2(*(__half2*)&v.y);
        acc0.x += a.x; acc0.y += a.y; acc0.z += b.x; acc0.w += b.y;
    }

    float4 bv = ((const float4*)bias)[lane];
    ((float4*)(out + (size_t)node * D))[lane] = make_float4(
        acc0.x + acc1.x + bv.x, acc0.y + acc1.y + bv.y,
        acc0.z + acc1.z + bv.z, acc0.w + acc1.w + bv.w);
}

// ---------------------------------------------------------------------------
// Launch: 2 kernels, graph-capturable (no sync, no alloc).
// ---------------------------------------------------------------------------
extern "C" void kernel_launch(void* const* d_in, const int* in_sizes, int n_in,
                              void* d_out, int out_size) {
    const float* feat = (const float*)d_in[0];  // [50000, 128] f32
    const void*  src  = d_in[1];                // [640000] int32/int64
    const void*  dst  = d_in[2];                // [640000] int32/int64
    const float* W    = (const float*)d_in[3];  // [128, 128] f32
    const float* b    = (const float*)d_in[4];  // [1, 128] f32
    float* out = (float*)d_out;                 // [50000, 128] f32

    mega_kernel<<<GRID_TOT, 256>>>(feat, W, src, dst);
    agg_kernel<<<(N_NODES * 32 + 255) / 256, 256>>>(b, out);
}

// round 14
// speedup vs baseline: 1.2389x; 1.0312x over previous
#include <cuda_runtime.h>
#include <cuda_bf16.h>
#include <cuda_fp16.h>
#include <cstdint>

#define N_NODES 50000
#define D 128
#define N_EDGES 640000
#define S_BLK 64                       // sort blocks (wave-1 resident: < 148)
#define GRID_TOT 296
#define NGB ((N_NODES + 127) / 128)    // 391 gemm tiles
#define CHUNK 4                        // scan items per sort thread
#define NT (S_BLK * 256)               // sort threads = 16384

// Packed fp32x2 FMA (sm_100+): one fma-pipe slot computes two lane-FMAs.
#define FMA2(acc, a, b) \
    asm("fma.rn.f32x2 %0, %1, %2, %0;" : "+l"(acc) : "l"(a), "l"(b))
#define SPLAT2(d, f) \
    asm("mov.b64 %0, {%1, %1};" : "=l"(d) : "f"(f))
#define UNPACK2(lo, hi, v) \
    asm("mov.b64 {%0, %1}, %2;" : "=f"(lo), "=f"(hi) : "l"(v))

// ---- device scratch (no allocs allowed; zero-initialized) ----
__device__ __half g_Yh[(size_t)N_NODES * D];  // feat @ W in fp16 (12.8 MB)
__device__ int   g_count[N_NODES];
__device__ int   g_offset[N_NODES];
__device__ int   g_bsum[S_BLK];
__device__ int   g_bbase[S_BLK];
__device__ int   g_src_sorted[N_EDGES];
__device__ int   g_is64;
__device__ unsigned g_bar_cnt;
__device__ unsigned g_tile;
__device__ unsigned g_done;

__device__ __forceinline__ void sort_barrier(unsigned target) {
    __syncthreads();
    if (threadIdx.x == 0) {
        __threadfence();
        atomicAdd(&g_bar_cnt, 1u);
        while (*((volatile unsigned*)&g_bar_cnt) < target) __nanosleep(64);
        __threadfence();
    }
    __syncthreads();
}

// ---------------------------------------------------------------------------
// Mega kernel (EXACT round-11/13 structure — measured best; do not touch).
//  blocks [0,S_BLK): sort chain then join gemm pool; rest: gemm tiles.
//  gemm: g_Yh = fp16(feat @ W), 128x128 tile, 8x4 f32x2 reg tile, Kc=32.
// ---------------------------------------------------------------------------
__global__ void __launch_bounds__(256)
mega_kernel(const float* __restrict__ feat, const float* __restrict__ W,
            const void* __restrict__ srcp, const void* __restrict__ dstp) {
    __shared__ float sA[128 * 33];   // A tile, stride-33 padded
    __shared__ float sB[32 * 128];   // B tile [k][col]
    __shared__ int   ss[256];        // sort scan workspace

    const int tid = threadIdx.x;

    if (blockIdx.x < S_BLK) {
        // ================= SORT CHAIN (proven, unchanged) =================
        const int b = blockIdx.x;
        const int st = b * 256 + tid;

        for (int i = st; i < N_NODES; i += NT) g_count[i] = 0;
        if (b == 0 && tid < 32) {
            // int32 read as int64 packs two indices; high half is a random
            // node index (nonzero w.p. ~1-2e-5) -> out-of-range identifies it.
            const long long* s64 = (const long long*)srcp;
            const long long* d64 = (const long long*)dstp;
            int bad = 0;
#pragma unroll
            for (int r = 0; r < 2; r++) {
                int i = tid + r * 32;
                long long a = s64[i], c = d64[i];
                bad |= (a < 0 || a >= N_NODES || c < 0 || c >= N_NODES);
            }
            unsigned m = __ballot_sync(0xFFFFFFFFu, bad);
            if (tid == 0) g_is64 = (m == 0u);
        }
        sort_barrier(1u * S_BLK);

        const int is64 = g_is64;
        {   // hist (4x batched for MLP)
            int e = st;
            if (is64) {
                const long long* dd = (const long long*)dstp;
                for (; e + 3 * NT < N_EDGES; e += 4 * NT) {
                    int d0 = (int)dd[e], d1 = (int)dd[e + NT];
                    int d2 = (int)dd[e + 2 * NT], d3 = (int)dd[e + 3 * NT];
                    atomicAdd(&g_count[d0], 1); atomicAdd(&g_count[d1], 1);
                    atomicAdd(&g_count[d2], 1); atomicAdd(&g_count[d3], 1);
                }
                for (; e < N_EDGES; e += NT) atomicAdd(&g_count[(int)dd[e]], 1);
            } else {
                const int* dd = (const int*)dstp;
                for (; e + 3 * NT < N_EDGES; e += 4 * NT) {
                    int d0 = dd[e], d1 = dd[e + NT];
                    int d2 = dd[e + 2 * NT], d3 = dd[e + 3 * NT];
                    atomicAdd(&g_count[d0], 1); atomicAdd(&g_count[d1], 1);
                    atomicAdd(&g_count[d2], 1); atomicAdd(&g_count[d3], 1);
                }
                for (; e < N_EDGES; e += NT) atomicAdd(&g_count[dd[e]], 1);
            }
        }
        sort_barrier(2u * S_BLK);

        // scan: per-thread sums + block scan
        const int g0 = st * CHUNK;
        int csum = 0, cv[CHUNK];
#pragma unroll
        for (int i = 0; i < CHUNK; i++) {
            int g = g0 + i;
            cv[i] = (g < N_NODES) ? g_count[g] : 0;
            csum += cv[i];
        }
        ss[tid] = csum;
        __syncthreads();
#pragma unroll
        for (int off = 1; off < 256; off <<= 1) {
            int v = ss[tid];
            int u = (tid >= off) ? ss[tid - off] : 0;
            __syncthreads();
            ss[tid] = v + u;
            __syncthreads();
        }
        const int texcl = ss[tid] - csum;
        if (tid == 255) g_bsum[b] = ss[255];
        sort_barrier(3u * S_BLK);

        if (b == 0) {
            int v0 = (tid < S_BLK) ? g_bsum[tid] : 0;
            ss[tid] = v0;
            __syncthreads();
#pragma unroll
            for (int off = 1; off < S_BLK; off <<= 1) {
                int v = ss[tid];
                int u = (tid >= off) ? ss[tid - off] : 0;
                __syncthreads();
                ss[tid] = v + u;
                __syncthreads();
            }
            if (tid < S_BLK) g_bbase[tid] = ss[tid] - v0;
        }
        sort_barrier(4u * S_BLK);

        {
            int run = g_bbase[b] + texcl;
#pragma unroll
            for (int i = 0; i < CHUNK; i++) {
                int g = g0 + i;
                if (g < N_NODES) g_offset[g] = run;
                run += cv[i];
            }
        }
        sort_barrier(5u * S_BLK);

        {   // scatter (4x batched)
            int e = st;
            if (is64) {
                const long long* dd = (const long long*)dstp;
                const long long* sv = (const long long*)srcp;
                for (; e + 3 * NT < N_EDGES; e += 4 * NT) {
                    int d0 = (int)dd[e],          s0 = (int)sv[e];
                    int d1 = (int)dd[e + NT],     s1 = (int)sv[e + NT];
                    int d2 = (int)dd[e + 2 * NT], s2 = (int)sv[e + 2 * NT];
                    int d3 = (int)dd[e + 3 * NT], s3 = (int)sv[e + 3 * NT];
                    int p0 = atomicAdd(&g_offset[d0], 1);
                    int p1 = atomicAdd(&g_offset[d1], 1);
                    int p2 = atomicAdd(&g_offset[d2], 1);
                    int p3 = atomicAdd(&g_offset[d3], 1);
                    g_src_sorted[p0] = s0; g_src_sorted[p1] = s1;
                    g_src_sorted[p2] = s2; g_src_sorted[p3] = s3;
                }
                for (; e < N_EDGES; e += NT)
                    g_src_sorted[atomicAdd(&g_offset[(int)dd[e]], 1)] = (int)sv[e];
            } else {
                const int* dd = (const int*)dstp;
                const int* sv = (const int*)srcp;
                for (; e + 3 * NT < N_EDGES; e += 4 * NT) {
                    int d0 = dd[e],          s0 = sv[e];
                    int d1 = dd[e + NT],     s1 = sv[e + NT];
                    int d2 = dd[e + 2 * NT], s2 = sv[e + 2 * NT];
                    int d3 = dd[e + 3 * NT], s3 = sv[e + 3 * NT];
                    int p0 = atomicAdd(&g_offset[d0], 1);
                    int p1 = atomicAdd(&g_offset[d1], 1);
                    int p2 = atomicAdd(&g_offset[d2], 1);
                    int p3 = atomicAdd(&g_offset[d3], 1);
                    g_src_sorted[p0] = s0; g_src_sorted[p1] = s1;
                    g_src_sorted[p2] = s2; g_src_sorted[p3] = s3;
                }
                for (; e < N_EDGES; e += NT)
                    g_src_sorted[atomicAdd(&g_offset[dd[e]], 1)] = sv[e];
            }
        }
        __syncthreads();
        // fall through: join the gemm tile pool
    }

    // ====== GEMM: g_Yh = fp16(feat @ W), f32x2 FMA, work-stealing ======
    const int tx = tid & 15;          // col group (8 cols = 4 f32x2 pairs)
    const int ty = tid >> 4;          // row group (8 rows)
    const int kq = tid & 7;           // A stage: f4 index in k-chunk
    const int ar0 = tid >> 3;         // A stage: row 0..31
    const int c4 = tid & 31;          // B stage: f4 col
    const int kr0 = tid >> 5;         // B stage: k row 0..7

    __shared__ unsigned s_tile;
    for (;;) {
        __syncthreads();
        if (tid == 0) s_tile = atomicAdd(&g_tile, 1u);
        __syncthreads();
        const unsigned tile = s_tile;
        if (tile >= NGB) break;
        const int row0 = (int)tile * 128;

        unsigned long long acc2[8][4];   // acc2[i][jp] = cols (2jp, 2jp+1)
#pragma unroll
        for (int i = 0; i < 8; i++)
#pragma unroll
            for (int j = 0; j < 4; j++) acc2[i][j] = 0ull;

        for (int k0 = 0; k0 < D; k0 += 32) {
#pragma unroll
            for (int p = 0; p < 4; p++) {
                int r = ar0 + p * 32;
                int row = row0 + r;
                float4 v = make_float4(0.f, 0.f, 0.f, 0.f);
                if (row < N_NODES)
                    v = *(const float4*)(feat + (size_t)row * D + k0 + kq * 4);
                float* dst = &sA[r * 33 + kq * 4];
                dst[0] = v.x; dst[1] = v.y; dst[2] = v.z; dst[3] = v.w;
            }
#pragma unroll
            for (int p = 0; p < 4; p++) {
                int kr = kr0 + p * 8;
                *(float4*)(sB + kr * 128 + c4 * 4) =
                    *(const float4*)(W + (size_t)(k0 + kr) * D + c4 * 4);
            }
            __syncthreads();

#pragma unroll 8
            for (int k = 0; k < 32; k++) {
                ulonglong2 bl0 = *(const ulonglong2*)(sB + k * 128 + tx * 8);
                ulonglong2 bl1 = *(const ulonglong2*)(sB + k * 128 + tx * 8 + 4);
                unsigned long long b2[4] = {bl0.x, bl0.y, bl1.x, bl1.y};
                unsigned long long a2[8];
#pragma unroll
                for (int i = 0; i < 8; i++) {
                    float av = sA[(ty * 8 + i) * 33 + k];
                    SPLAT2(a2[i], av);
                }
#pragma unroll
                for (int i = 0; i < 8; i++)
#pragma unroll
                    for (int j = 0; j < 4; j++) FMA2(acc2[i][j], a2[i], b2[j]);
            }
            __syncthreads();
        }

        // fp16 epilogue: each acc2 pair -> one half2; 16B store per row seg
#pragma unroll
        for (int i = 0; i < 8; i++) {
            int row = row0 + ty * 8 + i;
            if (row < N_NODES) {
                __half2 h[4];
#pragma unroll
                for (int j = 0; j < 4; j++) {
                    float lo, hi;
                    UNPACK2(lo, hi, acc2[i][j]);
                    h[j] = __floats2half2_rn(lo, hi);
                }
                *(uint4*)(g_Yh + (size_t)row * D + tx * 8) = *(uint4*)h;
            }
        }
    }

    // counter reset for next graph replay
    __syncthreads();
    if (tid == 0) {
        __threadfence();
        unsigned old = atomicAdd(&g_done, 1u);
        if (old == GRID_TOT - 1) { g_tile = 0; g_bar_cnt = 0; g_done = 0; }
    }
}

// ---------------------------------------------------------------------------
// Aggregation: out[n] = sum_{e in seg(n)} Yh[src_sorted[e]] + b.
// One warp per node; lane covers 4 cols (8B). 8-wide batches are reduced
// with a half2 pairwise TREE (14 HADD2) and converted to fp32 ONCE per
// batch (4 cvt + 4 add) — the loop was issue-bound on per-edge converts.
// fp16 tree error ~3e-4 rel, within the 1e-3 budget.
// ---------------------------------------------------------------------------
__global__ void __launch_bounds__(256) agg_kernel(const float* __restrict__ bias,
                                                  float* __restrict__ out) {
    int node = (blockIdx.x * blockDim.x + threadIdx.x) >> 5;
    int lane = threadIdx.x & 31;
    if (node >= N_NODES) return;

    const int end = g_offset[node];
    const int beg = end - g_count[node];

    float4 acc = make_float4(0.f, 0.f, 0.f, 0.f);
    int e = beg;
    for (; e + 7 < end; e += 8) {
        int s0 = g_src_sorted[e];
        int s1 = g_src_sorted[e + 1];
        int s2 = g_src_sorted[e + 2];
        int s3 = g_src_sorted[e + 3];
        int s4 = g_src_sorted[e + 4];
        int s5 = g_src_sorted[e + 5];
        int s6 = g_src_sorted[e + 6];
        int s7 = g_src_sorted[e + 7];
        uint2 v0 = ((const uint2*)(g_Yh + (size_t)s0 * D))[lane];
        uint2 v1 = ((const uint2*)(g_Yh + (size_t)s1 * D))[lane];
        uint2 v2 = ((const uint2*)(g_Yh + (size_t)s2 * D))[lane];
        uint2 v3 = ((const uint2*)(g_Yh + (size_t)s3 * D))[lane];
        uint2 v4 = ((const uint2*)(g_Yh + (size_t)s4 * D))[lane];
        uint2 v5 = ((const uint2*)(g_Yh + (size_t)s5 * D))[lane];
        uint2 v6 = ((const uint2*)(g_Yh + (size_t)s6 * D))[lane];
        uint2 v7 = ((const uint2*)(g_Yh + (size_t)s7 * D))[lane];
        // half2 pairwise tree over 8 edges, per column-pair
        __half2 x = __hadd2(
            __hadd2(__hadd2(*(__half2*)&v0.x, *(__half2*)&v1.x),
                    __hadd2(*(__half2*)&v2.x, *(__half2*)&v3.x)),
            __hadd2(__hadd2(*(__half2*)&v4.x, *(__half2*)&v5.x),
                    __hadd2(*(__half2*)&v6.x, *(__half2*)&v7.x)));
        __half2 y = __hadd2(
            __hadd2(__hadd2(*(__half2*)&v0.y, *(__half2*)&v1.y),
                    __hadd2(*(__half2*)&v2.y, *(__half2*)&v3.y)),
            __hadd2(__hadd2(*(__half2*)&v4.y, *(__half2*)&v5.y),
                    __hadd2(*(__half2*)&v6.y, *(__half2*)&v7.y)));
        float2 fx = __half22float2(x);
        float2 fy = __half22float2(y);
        acc.x += fx.x; acc.y += fx.y; acc.z += fy.x; acc.w += fy.y;
    }
    for (; e + 3 < end; e += 4) {
        int s0 = g_src_sorted[e];
        int s1 = g_src_sorted[e + 1];
        int s2 = g_src_sorted[e + 2];
        int s3 = g_src_sorted[e + 3];
        uint2 v0 = ((const uint2*)(g_Yh + (size_t)s0 * D))[lane];
        uint2 v1 = ((const uint2*)(g_Yh + (size_t)s1 * D))[lane];
        uint2 v2 = ((const uint2*)(g_Yh + (size_t)s2 * D))[lane];
        uint2 v3 = ((const uint2*)(g_Yh + (size_t)s3 * D))[lane];
        __half2 x = __hadd2(__hadd2(*(__half2*)&v0.x, *(__half2*)&v1.x),
                            __hadd2(*(__half2*)&v2.x, *(__half2*)&v3.x));
        __half2 y = __hadd2(__hadd2(*(__half2*)&v0.y, *(__half2*)&v1.y),
                            __hadd2(*(__half2*)&v2.y, *(__half2*)&v3.y));
        float2 fx = __half22float2(x);
        float2 fy = __half22float2(y);
        acc.x += fx.x; acc.y += fx.y; acc.z += fy.x; acc.w += fy.y;
    }
    for (; e < end; e++) {
        int s = g_src_sorted[e];
        uint2 v = ((const uint2*)(g_Yh + (size_t)s * D))[lane];
        float2 a = __half22float2(*(__half2*)&v.x);
        float2 b = __half22float2(*(__half2*)&v.y);
        acc.x += a.x; acc.y += a.y; acc.z += b.x; acc.w += b.y;
    }

    float4 bv = ((const float4*)bias)[lane];
    ((float4*)(out + (size_t)node * D))[lane] = make_float4(
        acc.x + bv.x, acc.y + bv.y, acc.z + bv.z, acc.w + bv.w);
}

// ---------------------------------------------------------------------------
// Launch: 2 kernels, graph-capturable (no sync, no alloc).
// ---------------------------------------------------------------------------
extern "C" void kernel_launch(void* const* d_in, const int* in_sizes, int n_in,
                              void* d_out, int out_size) {
    const float* feat = (const float*)d_in[0];  // [50000, 128] f32
    const void*  src  = d_in[1];                // [640000] int32/int64
    const void*  dst  = d_in[2];                // [640000] int32/int64
    const float* W    = (const float*)d_in[3];  // [128, 128] f32
    const float* b    = (const float*)d_in[4];  // [1, 128] f32
    float* out = (float*)d_out;                 // [50000, 128] f32

    mega_kernel<<<GRID_TOT, 256>>>(feat, W, src, dst);
    agg_kernel<<<(N_NODES * 32 + 255) / 256, 256>>>(b, out);
}